// round 1
// baseline (speedup 1.0000x reference)
#include <cuda_runtime.h>
#include <cuda_bf16.h>
#include <stdint.h>
#include <math.h>

#define NN   100000
#define NE   1600000
#define CIN  128
#define CHID 256
#define COUT 40

typedef __nv_bfloat16  bf16;
typedef __nv_bfloat162 bf162;

#define SCAN_T  1024
#define SCAN_NB ((NN + SCAN_T - 1) / SCAN_T)   // 98

// ---------------- device scratch (static: no allocations allowed) ----------------
__device__ int   g_deg[NN];
__device__ int   g_rowptr[NN + 1];
__device__ int   g_cursor[NN];
__device__ int   g_bsums[SCAN_NB];
__device__ int   g_csrc[NE];
__device__ float g_csw[NE];

__device__ bf16  g_xhi[(size_t)NN * CIN];
__device__ bf16  g_xlo[(size_t)NN * CIN];
__device__ bf16  g_h1hi[(size_t)NN * CHID];
__device__ bf16  g_h1lo[(size_t)NN * CHID];
__device__ bf16  g_h2hi[(size_t)NN * CHID];
__device__ bf16  g_h2lo[(size_t)NN * CHID];
__device__ bf16  g_aghi[(size_t)NN * CHID];
__device__ bf16  g_aglo[(size_t)NN * CHID];

__device__ bf16  g_w1hi[CHID * 2 * CIN];
__device__ bf16  g_w1lo[CHID * 2 * CIN];
__device__ bf16  g_w2hi[CHID * 2 * CHID];
__device__ bf16  g_w2lo[CHID * 2 * CHID];
__device__ bf16  g_w3hi[COUT * 2 * CHID];
__device__ bf16  g_w3lo[COUT * 2 * CHID];

__device__ float g_logits[(size_t)NN * COUT];

// ---------------- helpers ----------------
__device__ __forceinline__ void fsplit(float v, bf16 &hi, bf16 &lo) {
    hi = __float2bfloat16(v);
    lo = __float2bfloat16(v - __bfloat162float(hi));
}

__device__ __forceinline__ void mma16816(float *c, const uint32_t *a, const uint32_t *b) {
    asm volatile(
        "mma.sync.aligned.m16n8k16.row.col.f32.bf16.bf16.f32 "
        "{%0,%1,%2,%3}, {%4,%5,%6,%7}, {%8,%9}, {%0,%1,%2,%3};\n"
        : "+f"(c[0]), "+f"(c[1]), "+f"(c[2]), "+f"(c[3])
        : "r"(a[0]), "r"(a[1]), "r"(a[2]), "r"(a[3]), "r"(b[0]), "r"(b[1]));
}

// ---------------- CSR build ----------------
__global__ void k_zero_deg() {
    int i = blockIdx.x * blockDim.x + threadIdx.x;
    if (i < NN) g_deg[i] = 0;
}

__global__ void k_hist(const int *__restrict__ dst) {
    int e = blockIdx.x * blockDim.x + threadIdx.x;
    if (e < NE) atomicAdd(&g_deg[dst[e]], 1);
}

__global__ void k_scan1() {
    __shared__ int s[SCAN_T];
    int t = threadIdx.x;
    int g = blockIdx.x * SCAN_T + t;
    int v = (g < NN) ? g_deg[g] : 0;
    s[t] = v;
    __syncthreads();
    for (int o = 1; o < SCAN_T; o <<= 1) {
        int x = (t >= o) ? s[t - o] : 0;
        __syncthreads();
        s[t] += x;
        __syncthreads();
    }
    if (g < NN) g_rowptr[g + 1] = s[t];
    if (t == SCAN_T - 1) g_bsums[blockIdx.x] = s[t];
}

__global__ void k_scan2() {
    if (threadIdx.x == 0) {
        int run = 0;
        for (int i = 0; i < SCAN_NB; i++) {
            int v = g_bsums[i];
            g_bsums[i] = run;
            run += v;
        }
    }
}

__global__ void k_scan3() {
    int g = blockIdx.x * SCAN_T + threadIdx.x;
    if (g < NN) g_rowptr[g + 1] += g_bsums[blockIdx.x];
    if (g == 0) g_rowptr[0] = 0;
}

__global__ void k_cursor() {
    int g = blockIdx.x * blockDim.x + threadIdx.x;
    if (g < NN) g_cursor[g] = g_rowptr[g];
}

__global__ void k_fill(const int *__restrict__ src, const int *__restrict__ dst,
                       const float *__restrict__ ew) {
    int e = blockIdx.x * blockDim.x + threadIdx.x;
    if (e < NE) {
        int d = dst[e];
        int p = atomicAdd(&g_cursor[d], 1);
        g_csrc[p] = src[e];
        g_csw[p]  = ew[e];
    }
}

// ---------------- conversions ----------------
__global__ void k_split(const float *__restrict__ in, bf16 *__restrict__ hi,
                        bf16 *__restrict__ lo, int n) {
    int i = blockIdx.x * blockDim.x + threadIdx.x;
    if (i < n) fsplit(in[i], hi[i], lo[i]);
}

// W fp32 [K2 rows][M cols] row-major  ->  Wt hi/lo bf16 [M][K2]
__global__ void k_convW(const float *__restrict__ W, bf16 *__restrict__ whi,
                        bf16 *__restrict__ wlo, int K2, int M) {
    int i = blockIdx.x * blockDim.x + threadIdx.x;
    if (i < K2 * M) {
        int n = i / K2;
        int k = i - n * K2;
        fsplit(W[(size_t)k * M + n], whi[i], wlo[i]);
    }
}

// ---------------- aggregation (CSR, no atomics) ----------------
union U4 { uint2 u; bf16 b[4]; };
union U8 { uint4 u; bf16 b[8]; };

__global__ void k_agg128(const float *__restrict__ x) {
    int lane = threadIdx.x & 31, w = threadIdx.x >> 5;
    int node = blockIdx.x * 8 + w;
    if (node >= NN) return;
    int e0 = g_rowptr[node], e1 = g_rowptr[node + 1];
    float a0 = 0.f, a1 = 0.f, a2 = 0.f, a3 = 0.f;
    for (int e = e0; e < e1; e++) {
        int   s  = g_csrc[e];
        float wt = g_csw[e];
        float4 v = *(const float4 *)(x + (size_t)s * CIN + lane * 4);
        a0 += wt * v.x; a1 += wt * v.y; a2 += wt * v.z; a3 += wt * v.w;
    }
    U4 oh, ol;
    fsplit(a0, oh.b[0], ol.b[0]);
    fsplit(a1, oh.b[1], ol.b[1]);
    fsplit(a2, oh.b[2], ol.b[2]);
    fsplit(a3, oh.b[3], ol.b[3]);
    size_t off = (size_t)node * CIN + lane * 4;
    *(uint2 *)(g_aghi + off) = oh.u;
    *(uint2 *)(g_aglo + off) = ol.u;
}

__global__ void k_agg256(const bf16 *__restrict__ hhi, const bf16 *__restrict__ hlo) {
    int lane = threadIdx.x & 31, w = threadIdx.x >> 5;
    int node = blockIdx.x * 8 + w;
    if (node >= NN) return;
    int e0 = g_rowptr[node], e1 = g_rowptr[node + 1];
    float acc[8];
#pragma unroll
    for (int j = 0; j < 8; j++) acc[j] = 0.f;
    for (int e = e0; e < e1; e++) {
        int   s  = g_csrc[e];
        float wt = g_csw[e];
        uint4 uh = *(const uint4 *)(hhi + (size_t)s * CHID + lane * 8);
        uint4 ul = *(const uint4 *)(hlo + (size_t)s * CHID + lane * 8);
        const bf162 *ph = (const bf162 *)&uh;
        const bf162 *pl = (const bf162 *)&ul;
#pragma unroll
        for (int j = 0; j < 4; j++) {
            float2 fh = __bfloat1622float2(ph[j]);
            float2 fl = __bfloat1622float2(pl[j]);
            acc[2 * j]     += wt * (fh.x + fl.x);
            acc[2 * j + 1] += wt * (fh.y + fl.y);
        }
    }
    U8 oh, ol;
#pragma unroll
    for (int j = 0; j < 8; j++) fsplit(acc[j], oh.b[j], ol.b[j]);
    size_t off = (size_t)node * CHID + lane * 8;
    *(uint4 *)(g_aghi + off) = oh.u;
    *(uint4 *)(g_aglo + off) = ol.u;
}

// ---------------- GEMM: C[N, NOUT] = [A0 | A1] @ Wt^T + b ----------------
// A0/A1: hi/lo bf16 [N, KPART]. B: hi/lo bf16 [NOUT][2*KPART] (k-contiguous).
// Split product: C = Ahi*Bhi + Ahi*Blo + Alo*Bhi  (fp32 accum, ~2^-16 rel err)
template <int KPART, int NOUT, bool SPLIT>
__global__ __launch_bounds__(128) void k_gemm(
    const bf16 *__restrict__ Ah0, const bf16 *__restrict__ Al0,
    const bf16 *__restrict__ Ah1, const bf16 *__restrict__ Al1,
    const bf16 *__restrict__ Bh, const bf16 *__restrict__ Bl,
    const float *__restrict__ bias,
    bf16 *__restrict__ Chi, bf16 *__restrict__ Clo, float *__restrict__ Cf) {
    __shared__ bf16 Ash[128 * 16], Asl[128 * 16], Bsh[64 * 16], Bsl[64 * 16];

    int tid = threadIdx.x, lane = tid & 31, warp = tid >> 5;
    int wm = warp >> 1, wn = warp & 1;
    int rb = blockIdx.x, cb = blockIdx.y;

    float acc[4][4][4];
#pragma unroll
    for (int a = 0; a < 4; a++)
#pragma unroll
        for (int b = 0; b < 4; b++)
#pragma unroll
            for (int c = 0; c < 4; c++) acc[a][b][c] = 0.f;

    const int KT = (2 * KPART) / 16;
    for (int kt = 0; kt < KT; kt++) {
        int part = (kt * 16 >= KPART) ? 1 : 0;
        int kcol = kt * 16 - part * KPART;
        const bf16 *Ah = part ? Ah1 : Ah0;
        const bf16 *Al = part ? Al1 : Al0;

        // stage A tile: 128 rows x 16 k  (each thread: one row, 32B hi + 32B lo)
        {
            int r = tid, gr = rb * 128 + r;
            uint4 z = make_uint4(0, 0, 0, 0);
            uint4 v0 = z, v1 = z, w0 = z, w1 = z;
            if (gr < NN) {
                const uint4 *p = (const uint4 *)(Ah + (size_t)gr * KPART + kcol);
                v0 = p[0]; v1 = p[1];
                const uint4 *q = (const uint4 *)(Al + (size_t)gr * KPART + kcol);
                w0 = q[0]; w1 = q[1];
            }
            uint4 *dh = (uint4 *)(Ash + r * 16); dh[0] = v0; dh[1] = v1;
            uint4 *dl = (uint4 *)(Asl + r * 16); dl[0] = w0; dl[1] = w1;
        }
        // stage B tile: 64 n-rows x 16 k
        {
            int r = tid >> 1, half = tid & 1;
            int gn = cb * 64 + r;
            uint4 z = make_uint4(0, 0, 0, 0);
            uint4 vb = z, wb = z;
            if (gn < NOUT) {
                vb = *(const uint4 *)(Bh + (size_t)gn * (2 * KPART) + kt * 16 + half * 8);
                wb = *(const uint4 *)(Bl + (size_t)gn * (2 * KPART) + kt * 16 + half * 8);
            }
            *(uint4 *)(Bsh + r * 16 + half * 8) = vb;
            *(uint4 *)(Bsl + r * 16 + half * 8) = wb;
        }
        __syncthreads();

        const uint32_t *A32h = (const uint32_t *)Ash;
        const uint32_t *A32l = (const uint32_t *)Asl;
        const uint32_t *B32h = (const uint32_t *)Bsh;
        const uint32_t *B32l = (const uint32_t *)Bsl;

        uint32_t ah[4][4], al[4][4], bh[4][2], bl[4][2];
        int rbase = wm * 64 + (lane >> 2);
        int kq    = lane & 3;
#pragma unroll
        for (int mt = 0; mt < 4; mt++) {
            int rr = rbase + mt * 16;
            ah[mt][0] = A32h[rr * 8 + kq];
            ah[mt][1] = A32h[(rr + 8) * 8 + kq];
            ah[mt][2] = A32h[rr * 8 + kq + 4];
            ah[mt][3] = A32h[(rr + 8) * 8 + kq + 4];
            al[mt][0] = A32l[rr * 8 + kq];
            al[mt][1] = A32l[(rr + 8) * 8 + kq];
            al[mt][2] = A32l[rr * 8 + kq + 4];
            al[mt][3] = A32l[(rr + 8) * 8 + kq + 4];
        }
        int nb0 = wn * 32 + (lane >> 2);
#pragma unroll
        for (int nt = 0; nt < 4; nt++) {
            int nnr = nb0 + nt * 8;
            bh[nt][0] = B32h[nnr * 8 + kq];
            bh[nt][1] = B32h[nnr * 8 + kq + 4];
            bl[nt][0] = B32l[nnr * 8 + kq];
            bl[nt][1] = B32l[nnr * 8 + kq + 4];
        }
#pragma unroll
        for (int mt = 0; mt < 4; mt++)
#pragma unroll
            for (int nt = 0; nt < 4; nt++) {
                mma16816(acc[mt][nt], ah[mt], bh[nt]);
                mma16816(acc[mt][nt], ah[mt], bl[nt]);
                mma16816(acc[mt][nt], al[mt], bh[nt]);
            }
        __syncthreads();
    }

    // epilogue
#pragma unroll
    for (int mt = 0; mt < 4; mt++)
#pragma unroll
        for (int nt = 0; nt < 4; nt++) {
            int r0 = rb * 128 + wm * 64 + mt * 16 + (lane >> 2);
            int c0 = cb * 64 + wn * 32 + nt * 8 + (lane & 3) * 2;
            float b0 = (c0 < NOUT) ? bias[c0] : 0.f;
            float b1 = (c0 + 1 < NOUT) ? bias[c0 + 1] : 0.f;
            float *cc = acc[mt][nt];
            if (SPLIT) {
                if (r0 < NN) {
                    float v0 = fmaxf(cc[0] + b0, 0.f), v1 = fmaxf(cc[1] + b1, 0.f);
                    bf16 h0, l0, h1, l1;
                    fsplit(v0, h0, l0); fsplit(v1, h1, l1);
                    *(bf162 *)(Chi + (size_t)r0 * CHID + c0) = __halves2bfloat162(h0, h1);
                    *(bf162 *)(Clo + (size_t)r0 * CHID + c0) = __halves2bfloat162(l0, l1);
                }
                if (r0 + 8 < NN) {
                    float v0 = fmaxf(cc[2] + b0, 0.f), v1 = fmaxf(cc[3] + b1, 0.f);
                    bf16 h0, l0, h1, l1;
                    fsplit(v0, h0, l0); fsplit(v1, h1, l1);
                    *(bf162 *)(Chi + (size_t)(r0 + 8) * CHID + c0) = __halves2bfloat162(h0, h1);
                    *(bf162 *)(Clo + (size_t)(r0 + 8) * CHID + c0) = __halves2bfloat162(l0, l1);
                }
            } else {
                if (r0 < NN) {
                    if (c0 < NOUT)     Cf[(size_t)r0 * NOUT + c0]     = cc[0] + b0;
                    if (c0 + 1 < NOUT) Cf[(size_t)r0 * NOUT + c0 + 1] = cc[1] + b1;
                }
                if (r0 + 8 < NN) {
                    if (c0 < NOUT)     Cf[(size_t)(r0 + 8) * NOUT + c0]     = cc[2] + b0;
                    if (c0 + 1 < NOUT) Cf[(size_t)(r0 + 8) * NOUT + c0 + 1] = cc[3] + b1;
                }
            }
        }
}

// ---------------- log_softmax over 40 cols ----------------
__global__ void k_lsm(float *__restrict__ out) {
    int w = threadIdx.x >> 5, lane = threadIdx.x & 31;
    int row = blockIdx.x * 4 + w;
    if (row >= NN) return;
    const float *p = g_logits + (size_t)row * COUT;
    float v1 = p[lane];
    float v2 = (lane < 8) ? p[32 + lane] : -INFINITY;
    float m = fmaxf(v1, v2);
#pragma unroll
    for (int o = 16; o; o >>= 1) m = fmaxf(m, __shfl_xor_sync(0xffffffffu, m, o));
    float s = expf(v1 - m) + ((lane < 8) ? expf(v2 - m) : 0.f);
#pragma unroll
    for (int o = 16; o; o >>= 1) s += __shfl_xor_sync(0xffffffffu, s, o);
    float lse = m + logf(s);
    out[(size_t)row * COUT + lane] = v1 - lse;
    if (lane < 8) out[(size_t)row * COUT + 32 + lane] = v2 - lse;
}

// ---------------- launch ----------------
#define SYM(p, s) cudaGetSymbolAddress((void **)&(p), s)

extern "C" void kernel_launch(void *const *d_in, const int *in_sizes, int n_in,
                              void *d_out, int out_size) {
    const float *x  = (const float *)d_in[0];
    const int   *ei = (const int *)d_in[1];
    const float *ew = (const float *)d_in[2];
    const float *W1 = (const float *)d_in[3];
    const float *b1 = (const float *)d_in[4];
    const float *W2 = (const float *)d_in[5];
    const float *b2 = (const float *)d_in[6];
    const float *W3 = (const float *)d_in[7];
    const float *b3 = (const float *)d_in[8];
    float *out = (float *)d_out;
    const int *src = ei;
    const int *dst = ei + NE;

    bf16 *xhi, *xlo, *h1hi, *h1lo, *h2hi, *h2lo, *aghi, *aglo;
    bf16 *w1hi, *w1lo, *w2hi, *w2lo, *w3hi, *w3lo;
    float *logits;
    SYM(xhi, g_xhi);   SYM(xlo, g_xlo);
    SYM(h1hi, g_h1hi); SYM(h1lo, g_h1lo);
    SYM(h2hi, g_h2hi); SYM(h2lo, g_h2lo);
    SYM(aghi, g_aghi); SYM(aglo, g_aglo);
    SYM(w1hi, g_w1hi); SYM(w1lo, g_w1lo);
    SYM(w2hi, g_w2hi); SYM(w2lo, g_w2lo);
    SYM(w3hi, g_w3hi); SYM(w3lo, g_w3lo);
    SYM(logits, g_logits);

    // CSR build
    k_zero_deg<<<(NN + 255) / 256, 256>>>();
    k_hist<<<(NE + 255) / 256, 256>>>(dst);
    k_scan1<<<SCAN_NB, SCAN_T>>>();
    k_scan2<<<1, 32>>>();
    k_scan3<<<SCAN_NB, SCAN_T>>>();
    k_cursor<<<(NN + 255) / 256, 256>>>();
    k_fill<<<(NE + 255) / 256, 256>>>(src, dst, ew);

    // conversions
    k_split<<<(NN * CIN + 255) / 256, 256>>>(x, xhi, xlo, NN * CIN);
    k_convW<<<(CHID * 2 * CIN + 255) / 256, 256>>>(W1, w1hi, w1lo, 2 * CIN, CHID);
    k_convW<<<(CHID * 2 * CHID + 255) / 256, 256>>>(W2, w2hi, w2lo, 2 * CHID, CHID);
    k_convW<<<(COUT * 2 * CHID + 255) / 256, 256>>>(W3, w3hi, w3lo, 2 * CHID, COUT);

    dim3 gHID((NN + 127) / 128, CHID / 64);
    dim3 gOUT((NN + 127) / 128, 1);

    // layer 1
    k_agg128<<<(NN + 7) / 8, 256>>>(x);
    k_gemm<CIN, CHID, true><<<gHID, 128>>>(xhi, xlo, aghi, aglo, w1hi, w1lo, b1,
                                           h1hi, h1lo, nullptr);
    // layer 2
    k_agg256<<<(NN + 7) / 8, 256>>>(h1hi, h1lo);
    k_gemm<CHID, CHID, true><<<gHID, 128>>>(h1hi, h1lo, aghi, aglo, w2hi, w2lo, b2,
                                            h2hi, h2lo, nullptr);
    // layer 3
    k_agg256<<<(NN + 7) / 8, 256>>>(h2hi, h2lo);
    k_gemm<CHID, COUT, false><<<gOUT, 128>>>(h2hi, h2lo, aghi, aglo, w3hi, w3lo, b3,
                                             nullptr, nullptr, logits);
    k_lsm<<<(NN + 3) / 4, 128>>>(out);
}

// round 5
// speedup vs baseline: 1.4786x; 1.4786x over previous
#include <cuda_runtime.h>
#include <cuda_bf16.h>
#include <stdint.h>
#include <math.h>

#define NN   100000
#define NE   1600000
#define CIN  128
#define CHID 256
#define COUT 40
#define P3W  80          // layer-3 pre-agg width (40 self + 40 agg-input)

typedef __nv_bfloat16  bf16;
typedef __nv_bfloat162 bf162;

#define SCAN_T  1024
#define SCAN_NB ((NN + SCAN_T - 1) / SCAN_T)   // 98

// ---------------- device scratch ----------------
__device__ int   g_deg[NN];
__device__ int   g_rowptr[NN + 1];
__device__ int   g_cursor[NN];
__device__ int   g_bsums[SCAN_NB];
__device__ int2  g_cpack[NE];          // (src, weight bits)

__device__ bf16  g_xhi[(size_t)NN * CIN];
__device__ bf16  g_xlo[(size_t)NN * CIN];
__device__ bf16  g_h1hi[(size_t)NN * CHID];
__device__ bf16  g_h1lo[(size_t)NN * CHID];
__device__ bf16  g_h2hi[(size_t)NN * CHID];
__device__ bf16  g_h2lo[(size_t)NN * CHID];
__device__ bf16  g_aghi[(size_t)NN * CHID];
__device__ bf16  g_aglo[(size_t)NN * CHID];

__device__ bf16  g_w1hi[CHID * 2 * CIN];
__device__ bf16  g_w1lo[CHID * 2 * CIN];
__device__ bf16  g_w2hi[CHID * 2 * CHID];
__device__ bf16  g_w2lo[CHID * 2 * CHID];
__device__ bf16  g_w3hi[P3W * CHID];          // [80][256], k-contiguous (K2=256)
__device__ bf16  g_w3lo[P3W * CHID];

__device__ float g_p3[(size_t)NN * P3W];

// ---------------- helpers ----------------
__device__ __forceinline__ void fsplit(float v, bf16 &hi, bf16 &lo) {
    hi = __float2bfloat16(v);
    lo = __float2bfloat16(v - __bfloat162float(hi));
}

__device__ __forceinline__ void mma16816(float *c, const uint32_t *a, const uint32_t *b) {
    asm volatile(
        "mma.sync.aligned.m16n8k16.row.col.f32.bf16.bf16.f32 "
        "{%0,%1,%2,%3}, {%4,%5,%6,%7}, {%8,%9}, {%0,%1,%2,%3};\n"
        : "+f"(c[0]), "+f"(c[1]), "+f"(c[2]), "+f"(c[3])
        : "r"(a[0]), "r"(a[1]), "r"(a[2]), "r"(a[3]), "r"(b[0]), "r"(b[1]));
}

__device__ __forceinline__ void cp_async16(uint32_t d, const void *s, bool p) {
    asm volatile("cp.async.cg.shared.global [%0], [%1], 16, %2;\n"
                 :: "r"(d), "l"(s), "r"(p ? 16 : 0));
}
__device__ __forceinline__ void cp_commit() { asm volatile("cp.async.commit_group;\n"); }
template <int N> __device__ __forceinline__ void cp_wait() {
    asm volatile("cp.async.wait_group %0;\n" :: "n"(N));
}

// ---------------- CSR build ----------------
__global__ void k_zero_deg() {
    int i = blockIdx.x * blockDim.x + threadIdx.x;
    if (i < NN) g_deg[i] = 0;
}

__global__ void k_hist(const int *__restrict__ dst) {
    int e = blockIdx.x * blockDim.x + threadIdx.x;
    if (e < NE) atomicAdd(&g_deg[dst[e]], 1);
}

__global__ void k_scan1() {
    __shared__ int s[SCAN_T];
    int t = threadIdx.x;
    int g = blockIdx.x * SCAN_T + t;
    int v = (g < NN) ? g_deg[g] : 0;
    s[t] = v;
    __syncthreads();
    for (int o = 1; o < SCAN_T; o <<= 1) {
        int x = (t >= o) ? s[t - o] : 0;
        __syncthreads();
        s[t] += x;
        __syncthreads();
    }
    if (g < NN) g_rowptr[g + 1] = s[t];
    if (t == SCAN_T - 1) g_bsums[blockIdx.x] = s[t];
}

__global__ void k_scan2() {     // parallel exclusive scan of 98 block sums
    __shared__ int s[128];
    int t = threadIdx.x;
    int v = (t < SCAN_NB) ? g_bsums[t] : 0;
    s[t] = v;
    __syncthreads();
    for (int o = 1; o < 128; o <<= 1) {
        int x = (t >= o) ? s[t - o] : 0;
        __syncthreads();
        s[t] += x;
        __syncthreads();
    }
    if (t < SCAN_NB) g_bsums[t] = s[t] - v;
}

__global__ void k_scan3() {     // finalize rowptr + init cursor
    int g = blockIdx.x * SCAN_T + threadIdx.x;
    if (g < NN) {
        int v = g_rowptr[g + 1] + g_bsums[blockIdx.x];
        g_rowptr[g + 1] = v;
        g_cursor[g] = v - g_deg[g];
    }
    if (g == 0) g_rowptr[0] = 0;
}

__global__ void k_fill(const int *__restrict__ src, const int *__restrict__ dst,
                       const float *__restrict__ ew) {
    int e = blockIdx.x * blockDim.x + threadIdx.x;
    if (e < NE) {
        int d = dst[e];
        int p = atomicAdd(&g_cursor[d], 1);
        g_cpack[p] = make_int2(src[e], __float_as_int(ew[e]));
    }
}

// ---------------- conversions ----------------
__global__ void k_split(const float *__restrict__ in, bf16 *__restrict__ hi,
                        bf16 *__restrict__ lo, int n) {
    int i = blockIdx.x * blockDim.x + threadIdx.x;
    if (i < n) fsplit(in[i], hi[i], lo[i]);
}

// W fp32 [K2 rows][M cols] row-major  ->  B hi/lo bf16 [M][K2] (k-contiguous)
__global__ void k_convW(const float *__restrict__ W, bf16 *__restrict__ whi,
                        bf16 *__restrict__ wlo, int K2, int M) {
    int i = blockIdx.x * blockDim.x + threadIdx.x;
    if (i < K2 * M) {
        int n = i / K2;
        int k = i - n * K2;
        fsplit(W[(size_t)k * M + n], whi[i], wlo[i]);
    }
}

// W3 [512][40] fp32 -> B3 [80][256] bf16 hi/lo, k-contiguous with stride CHID=256.
//   n <  40: B3[n][k] = W3[k][n]            (self half, rows 0..255)
//   n >= 40: B3[n][k] = W3[256 + k][n - 40] (aggregate half, rows 256..511)
__global__ void k_convW3(const float *__restrict__ W3) {
    int i = blockIdx.x * blockDim.x + threadIdx.x;
    if (i < P3W * CHID) {
        int n = i / CHID;
        int k = i - n * CHID;
        float v = (n < COUT) ? W3[(size_t)k * COUT + n]
                             : W3[(size_t)(CHID + k) * COUT + (n - COUT)];
        fsplit(v, g_w3hi[i], g_w3lo[i]);
    }
}

// ---------------- aggregation (CSR, no atomics) ----------------
union U4 { uint2 u; bf16 b[4]; };
union U8 { uint4 u; bf16 b[8]; };

__global__ void k_agg128(const float *__restrict__ x) {
    int lane = threadIdx.x & 31, w = threadIdx.x >> 5;
    int node = blockIdx.x * 8 + w;
    if (node >= NN) return;
    int e0 = g_rowptr[node], e1 = g_rowptr[node + 1];
    float a0 = 0.f, a1 = 0.f, a2 = 0.f, a3 = 0.f;
    for (int e = e0; e < e1; e++) {
        int2  pk = g_cpack[e];
        float wt = __int_as_float(pk.y);
        float4 v = *(const float4 *)(x + (size_t)pk.x * CIN + lane * 4);
        a0 += wt * v.x; a1 += wt * v.y; a2 += wt * v.z; a3 += wt * v.w;
    }
    U4 oh, ol;
    fsplit(a0, oh.b[0], ol.b[0]);
    fsplit(a1, oh.b[1], ol.b[1]);
    fsplit(a2, oh.b[2], ol.b[2]);
    fsplit(a3, oh.b[3], ol.b[3]);
    size_t off = (size_t)node * CIN + lane * 4;
    *(uint2 *)(g_aghi + off) = oh.u;
    *(uint2 *)(g_aglo + off) = ol.u;
}

__global__ void k_agg256(const bf16 *__restrict__ hhi, const bf16 *__restrict__ hlo) {
    int lane = threadIdx.x & 31, w = threadIdx.x >> 5;
    int node = blockIdx.x * 8 + w;
    if (node >= NN) return;
    int e0 = g_rowptr[node], e1 = g_rowptr[node + 1];
    float acc[8];
#pragma unroll
    for (int j = 0; j < 8; j++) acc[j] = 0.f;
    for (int e = e0; e < e1; e++) {
        int2  pk = g_cpack[e];
        float wt = __int_as_float(pk.y);
        uint4 uh = *(const uint4 *)(hhi + (size_t)pk.x * CHID + lane * 8);
        uint4 ul = *(const uint4 *)(hlo + (size_t)pk.x * CHID + lane * 8);
        const bf162 *ph = (const bf162 *)&uh;
        const bf162 *pl = (const bf162 *)&ul;
#pragma unroll
        for (int j = 0; j < 4; j++) {
            float2 fh = __bfloat1622float2(ph[j]);
            float2 fl = __bfloat1622float2(pl[j]);
            acc[2 * j]     += wt * (fh.x + fl.x);
            acc[2 * j + 1] += wt * (fh.y + fl.y);
        }
    }
    U8 oh, ol;
#pragma unroll
    for (int j = 0; j < 8; j++) fsplit(acc[j], oh.b[j], ol.b[j]);
    size_t off = (size_t)node * CHID + lane * 8;
    *(uint4 *)(g_aghi + off) = oh.u;
    *(uint4 *)(g_aglo + off) = ol.u;
}

// ---------------- GEMM: 128x128 block tile, 8 warps, 3-stage cp.async ----------------
// A0/A1: hi/lo bf16 [N, KPART] (two k-parts). B: hi/lo bf16 [NOUT][K2].
// Split product: C = Ahi*Bhi + Ahi*Blo + Alo*Bhi  (fp32 accum)
#define STAGES 3

template <int K2, int KPART, int NOUT, bool SPLIT>
__global__ __launch_bounds__(256, 1) void k_gemm(
    const bf16 *__restrict__ Ah0, const bf16 *__restrict__ Al0,
    const bf16 *__restrict__ Ah1, const bf16 *__restrict__ Al1,
    const bf16 *__restrict__ Bh, const bf16 *__restrict__ Bl,
    const float *__restrict__ bias,
    bf16 *__restrict__ Chi, bf16 *__restrict__ Clo, float *__restrict__ Cf) {

    // [stage][Ah,Al,Bh,Bl][128 rows * 16 k]
    __shared__ bf16 sm[STAGES][4][128 * 16];

    int tid = threadIdx.x, lane = tid & 31, warp = tid >> 5;
    int wm = warp >> 2, wn = warp & 3;            // 2 x 4 warp grid, warp tile 64x32
    int rb = blockIdx.x, cb = blockIdx.y;

    const int KT = K2 / 16;

    float acc[4][4][4];
#pragma unroll
    for (int a = 0; a < 4; a++)
#pragma unroll
        for (int b = 0; b < 4; b++)
#pragma unroll
            for (int c = 0; c < 4; c++) acc[a][b][c] = 0.f;

    // staging: thread t covers (row = t>>1, half = t&1) of each of the 4 tiles
    int sr = tid >> 1, sh = tid & 1;
    int a_gr = rb * 128 + sr;
    int b_gn = cb * 128 + sr;
    bool a_ok = a_gr < NN;
    bool b_ok = b_gn < NOUT;
    int a_grc = a_ok ? a_gr : 0;
    int b_gnc = b_ok ? b_gn : 0;

    auto issue = [&](int kt, int buf) {
        int part = (kt * 16 >= KPART) ? 1 : 0;
        int kcol = kt * 16 - part * KPART;
        const bf16 *Ah = part ? Ah1 : Ah0;
        const bf16 *Al = part ? Al1 : Al0;
        uint32_t base = (uint32_t)__cvta_generic_to_shared(&sm[buf][0][0]);
        uint32_t off  = (uint32_t)(sr * 16 + sh * 8) * 2;
        cp_async16(base + off,              Ah + (size_t)a_grc * KPART + kcol + sh * 8, a_ok);
        cp_async16(base + 4096 + off,       Al + (size_t)a_grc * KPART + kcol + sh * 8, a_ok);
        cp_async16(base + 8192 + off,       Bh + (size_t)b_gnc * K2 + kt * 16 + sh * 8, b_ok);
        cp_async16(base + 12288 + off,      Bl + (size_t)b_gnc * K2 + kt * 16 + sh * 8, b_ok);
    };

#pragma unroll
    for (int s = 0; s < STAGES - 1; s++) {
        issue(s, s);
        cp_commit();
    }

    for (int kt = 0; kt < KT; kt++) {
        cp_wait<STAGES - 2>();
        __syncthreads();
        int nk = kt + STAGES - 1;
        if (nk < KT) issue(nk, nk % STAGES);
        cp_commit();

        int buf = kt % STAGES;
        const uint32_t *A32h = (const uint32_t *)sm[buf][0];
        const uint32_t *A32l = (const uint32_t *)sm[buf][1];
        const uint32_t *B32h = (const uint32_t *)sm[buf][2];
        const uint32_t *B32l = (const uint32_t *)sm[buf][3];

        uint32_t ah[4][4], al[4][4], bh[4][2], bl[4][2];
        int rbase = wm * 64 + (lane >> 2);
        int kq    = lane & 3;
#pragma unroll
        for (int mt = 0; mt < 4; mt++) {
            int rr = rbase + mt * 16;
            ah[mt][0] = A32h[rr * 8 + kq];
            ah[mt][1] = A32h[(rr + 8) * 8 + kq];
            ah[mt][2] = A32h[rr * 8 + kq + 4];
            ah[mt][3] = A32h[(rr + 8) * 8 + kq + 4];
            al[mt][0] = A32l[rr * 8 + kq];
            al[mt][1] = A32l[(rr + 8) * 8 + kq];
            al[mt][2] = A32l[rr * 8 + kq + 4];
            al[mt][3] = A32l[(rr + 8) * 8 + kq + 4];
        }
        int nb0 = wn * 32 + (lane >> 2);
#pragma unroll
        for (int nt = 0; nt < 4; nt++) {
            int nnr = nb0 + nt * 8;
            bh[nt][0] = B32h[nnr * 8 + kq];
            bh[nt][1] = B32h[nnr * 8 + kq + 4];
            bl[nt][0] = B32l[nnr * 8 + kq];
            bl[nt][1] = B32l[nnr * 8 + kq + 4];
        }
#pragma unroll
        for (int mt = 0; mt < 4; mt++)
#pragma unroll
            for (int nt = 0; nt < 4; nt++) {
                mma16816(acc[mt][nt], ah[mt], bh[nt]);
                mma16816(acc[mt][nt], ah[mt], bl[nt]);
                mma16816(acc[mt][nt], al[mt], bh[nt]);
            }
        __syncthreads();
    }

    // epilogue
#pragma unroll
    for (int mt = 0; mt < 4; mt++)
#pragma unroll
        for (int nt = 0; nt < 4; nt++) {
            int r0 = rb * 128 + wm * 64 + mt * 16 + (lane >> 2);
            int c0 = cb * 128 + wn * 32 + nt * 8 + (lane & 3) * 2;
            float *cc = acc[mt][nt];
            if (SPLIT) {
                float b0 = bias[c0], b1 = bias[c0 + 1];
                if (r0 < NN) {
                    float v0 = fmaxf(cc[0] + b0, 0.f), v1 = fmaxf(cc[1] + b1, 0.f);
                    bf16 h0, l0, h1, l1;
                    fsplit(v0, h0, l0); fsplit(v1, h1, l1);
                    *(bf162 *)(Chi + (size_t)r0 * CHID + c0) = __halves2bfloat162(h0, h1);
                    *(bf162 *)(Clo + (size_t)r0 * CHID + c0) = __halves2bfloat162(l0, l1);
                }
                if (r0 + 8 < NN) {
                    float v0 = fmaxf(cc[2] + b0, 0.f), v1 = fmaxf(cc[3] + b1, 0.f);
                    bf16 h0, l0, h1, l1;
                    fsplit(v0, h0, l0); fsplit(v1, h1, l1);
                    *(bf162 *)(Chi + (size_t)(r0 + 8) * CHID + c0) = __halves2bfloat162(h0, h1);
                    *(bf162 *)(Clo + (size_t)(r0 + 8) * CHID + c0) = __halves2bfloat162(l0, l1);
                }
            } else {
                if (r0 < NN) {
                    if (c0 < NOUT)     Cf[(size_t)r0 * NOUT + c0]     = cc[0];
                    if (c0 + 1 < NOUT) Cf[(size_t)r0 * NOUT + c0 + 1] = cc[1];
                }
                if (r0 + 8 < NN) {
                    if (c0 < NOUT)     Cf[(size_t)(r0 + 8) * NOUT + c0]     = cc[2];
                    if (c0 + 1 < NOUT) Cf[(size_t)(r0 + 8) * NOUT + c0 + 1] = cc[3];
                }
            }
        }
}

// ---------------- fused layer-3 tail: agg(d=40) + self + bias + log_softmax ----------------
__global__ void k_final(const float *__restrict__ b3, float *__restrict__ out) {
    int w = threadIdx.x >> 5, lane = threadIdx.x & 31;
    int node = blockIdx.x * 8 + w;
    if (node >= NN) return;
    int e0 = g_rowptr[node], e1 = g_rowptr[node + 1];
    float a0 = 0.f, a1 = 0.f;
    for (int e = e0; e < e1; e++) {
        int2  pk = g_cpack[e];
        float wt = __int_as_float(pk.y);
        const float *pb = g_p3 + (size_t)pk.x * P3W + COUT;
        a0 += wt * pb[lane];
        if (lane < 8) a1 += wt * pb[32 + lane];
    }
    const float *ps = g_p3 + (size_t)node * P3W;
    float v1 = ps[lane] + a0 + b3[lane];
    float v2 = (lane < 8) ? ps[32 + lane] + a1 + b3[32 + lane] : -INFINITY;
    float m = fmaxf(v1, v2);
#pragma unroll
    for (int o = 16; o; o >>= 1) m = fmaxf(m, __shfl_xor_sync(0xffffffffu, m, o));
    float s = expf(v1 - m) + ((lane < 8) ? expf(v2 - m) : 0.f);
#pragma unroll
    for (int o = 16; o; o >>= 1) s += __shfl_xor_sync(0xffffffffu, s, o);
    float lse = m + logf(s);
    out[(size_t)node * COUT + lane] = v1 - lse;
    if (lane < 8) out[(size_t)node * COUT + 32 + lane] = v2 - lse;
}

// ---------------- launch ----------------
#define SYM(p, s) cudaGetSymbolAddress((void **)&(p), s)

extern "C" void kernel_launch(void *const *d_in, const int *in_sizes, int n_in,
                              void *d_out, int out_size) {
    const float *x  = (const float *)d_in[0];
    const int   *ei = (const int *)d_in[1];
    const float *ew = (const float *)d_in[2];
    const float *W1 = (const float *)d_in[3];
    const float *b1 = (const float *)d_in[4];
    const float *W2 = (const float *)d_in[5];
    const float *b2 = (const float *)d_in[6];
    const float *W3 = (const float *)d_in[7];
    const float *b3 = (const float *)d_in[8];
    float *out = (float *)d_out;
    const int *src = ei;
    const int *dst = ei + NE;

    bf16 *xhi, *xlo, *h1hi, *h1lo, *h2hi, *h2lo, *aghi, *aglo;
    bf16 *w1hi, *w1lo, *w2hi, *w2lo, *w3hi, *w3lo;
    float *p3;
    SYM(xhi, g_xhi);   SYM(xlo, g_xlo);
    SYM(h1hi, g_h1hi); SYM(h1lo, g_h1lo);
    SYM(h2hi, g_h2hi); SYM(h2lo, g_h2lo);
    SYM(aghi, g_aghi); SYM(aglo, g_aglo);
    SYM(w1hi, g_w1hi); SYM(w1lo, g_w1lo);
    SYM(w2hi, g_w2hi); SYM(w2lo, g_w2lo);
    SYM(w3hi, g_w3hi); SYM(w3lo, g_w3lo);
    SYM(p3, g_p3);

    // CSR build
    k_zero_deg<<<(NN + 255) / 256, 256>>>();
    k_hist<<<(NE + 255) / 256, 256>>>(dst);
    k_scan1<<<SCAN_NB, SCAN_T>>>();
    k_scan2<<<1, 128>>>();
    k_scan3<<<SCAN_NB, SCAN_T>>>();
    k_fill<<<(NE + 255) / 256, 256>>>(src, dst, ew);

    // conversions
    k_split<<<(NN * CIN + 255) / 256, 256>>>(x, xhi, xlo, NN * CIN);
    k_convW<<<(CHID * 2 * CIN + 255) / 256, 256>>>(W1, w1hi, w1lo, 2 * CIN, CHID);
    k_convW<<<(CHID * 2 * CHID + 255) / 256, 256>>>(W2, w2hi, w2lo, 2 * CHID, CHID);
    k_convW3<<<(P3W * CHID + 255) / 256, 256>>>(W3);

    dim3 gHID((NN + 127) / 128, 2);
    dim3 gP3((NN + 127) / 128, 1);

    // layer 1
    k_agg128<<<(NN + 7) / 8, 256>>>(x);
    k_gemm<256, CIN, CHID, true><<<gHID, 256>>>(xhi, xlo, aghi, aglo, w1hi, w1lo, b1,
                                                h1hi, h1lo, nullptr);
    // layer 2
    k_agg256<<<(NN + 7) / 8, 256>>>(h1hi, h1lo);
    k_gemm<512, CHID, CHID, true><<<gHID, 256>>>(h1hi, h1lo, aghi, aglo, w2hi, w2lo, b2,
                                                 h2hi, h2lo, nullptr);
    // layer 3: GEMM first (h2 @ [W3_top|W3_bot] -> P[100k][80]), then fused agg tail
    k_gemm<256, 256, P3W, false><<<gP3, 256>>>(h2hi, h2lo, h2hi, h2lo, w3hi, w3lo, nullptr,
                                               nullptr, nullptr, p3);
    k_final<<<(NN + 7) / 8, 256>>>(b3, out);
}

// round 7
// speedup vs baseline: 1.5117x; 1.0224x over previous
#include <cuda_runtime.h>
#include <cuda_bf16.h>
#include <stdint.h>
#include <math.h>

#define NN   100000
#define NE   1600000
#define CIN  128
#define CHID 256
#define COUT 40
#define P3W  80          // layer-3 pre-agg width (40 self + 40 agg-input)

typedef __nv_bfloat16  bf16;
typedef __nv_bfloat162 bf162;

#define SCAN_T  1024
#define SCAN_NB ((NN + SCAN_T - 1) / SCAN_T)   // 98

// ---------------- device scratch ----------------
__device__ int   g_deg[NN];
__device__ int   g_rowptr[NN + 1];
__device__ int   g_cursor[NN];
__device__ int   g_bsums[SCAN_NB];
__device__ int2  g_cpack[NE];          // (src, weight bits)

__device__ bf16  g_xhi[(size_t)NN * CIN];
__device__ bf16  g_xlo[(size_t)NN * CIN];
__device__ bf16  g_h1hi[(size_t)NN * CHID];
__device__ bf16  g_h1lo[(size_t)NN * CHID];
__device__ bf16  g_h2hi[(size_t)NN * CHID];
__device__ bf16  g_h2lo[(size_t)NN * CHID];
__device__ bf16  g_aghi[(size_t)NN * CHID];
__device__ bf16  g_aglo[(size_t)NN * CHID];

__device__ bf16  g_w1hi[CHID * 2 * CIN];
__device__ bf16  g_w1lo[CHID * 2 * CIN];
__device__ bf16  g_w2hi[CHID * 2 * CHID];
__device__ bf16  g_w2lo[CHID * 2 * CHID];
__device__ bf16  g_w3hi[P3W * CHID];          // [80][256], k-contiguous (K2=256)
__device__ bf16  g_w3lo[P3W * CHID];

__device__ float g_p3[(size_t)NN * P3W];

// ---------------- helpers ----------------
__device__ __forceinline__ void fsplit(float v, bf16 &hi, bf16 &lo) {
    hi = __float2bfloat16(v);
    lo = __float2bfloat16(v - __bfloat162float(hi));
}

__device__ __forceinline__ void mma16816(float *c, const uint32_t *a, const uint32_t *b) {
    asm volatile(
        "mma.sync.aligned.m16n8k16.row.col.f32.bf16.bf16.f32 "
        "{%0,%1,%2,%3}, {%4,%5,%6,%7}, {%8,%9}, {%0,%1,%2,%3};\n"
        : "+f"(c[0]), "+f"(c[1]), "+f"(c[2]), "+f"(c[3])
        : "r"(a[0]), "r"(a[1]), "r"(a[2]), "r"(a[3]), "r"(b[0]), "r"(b[1]));
}

__device__ __forceinline__ void cp_async16(uint32_t d, const void *s, bool p) {
    asm volatile("cp.async.cg.shared.global [%0], [%1], 16, %2;\n"
                 :: "r"(d), "l"(s), "r"(p ? 16 : 0));
}
__device__ __forceinline__ void cp_commit() { asm volatile("cp.async.commit_group;\n"); }
template <int N> __device__ __forceinline__ void cp_wait() {
    asm volatile("cp.async.wait_group %0;\n" :: "n"(N));
}

// ---------------- CSR build ----------------
__global__ void k_zero_deg() {
    int i = blockIdx.x * blockDim.x + threadIdx.x;
    if (i < NN) g_deg[i] = 0;
}

__global__ void k_hist(const int *__restrict__ dst) {
    int e = blockIdx.x * blockDim.x + threadIdx.x;
    if (e < NE) atomicAdd(&g_deg[dst[e]], 1);
}

__global__ void k_scan1() {
    __shared__ int s[SCAN_T];
    int t = threadIdx.x;
    int g = blockIdx.x * SCAN_T + t;
    int v = (g < NN) ? g_deg[g] : 0;
    s[t] = v;
    __syncthreads();
    for (int o = 1; o < SCAN_T; o <<= 1) {
        int x = (t >= o) ? s[t - o] : 0;
        __syncthreads();
        s[t] += x;
        __syncthreads();
    }
    if (g < NN) g_rowptr[g + 1] = s[t];
    if (t == SCAN_T - 1) g_bsums[blockIdx.x] = s[t];
}

__global__ void k_scan2() {
    __shared__ int s[128];
    int t = threadIdx.x;
    int v = (t < SCAN_NB) ? g_bsums[t] : 0;
    s[t] = v;
    __syncthreads();
    for (int o = 1; o < 128; o <<= 1) {
        int x = (t >= o) ? s[t - o] : 0;
        __syncthreads();
        s[t] += x;
        __syncthreads();
    }
    if (t < SCAN_NB) g_bsums[t] = s[t] - v;
}

__global__ void k_scan3() {
    int g = blockIdx.x * SCAN_T + threadIdx.x;
    if (g < NN) {
        int v = g_rowptr[g + 1] + g_bsums[blockIdx.x];
        g_rowptr[g + 1] = v;
        g_cursor[g] = v - g_deg[g];
    }
    if (g == 0) g_rowptr[0] = 0;
}

__global__ void k_fill(const int *__restrict__ src, const int *__restrict__ dst,
                       const float *__restrict__ ew) {
    int e = blockIdx.x * blockDim.x + threadIdx.x;
    if (e < NE) {
        int d = dst[e];
        int p = atomicAdd(&g_cursor[d], 1);
        g_cpack[p] = make_int2(src[e], __float_as_int(ew[e]));
    }
}

// ---------------- conversions ----------------
__global__ void k_split(const float *__restrict__ in, bf16 *__restrict__ hi,
                        bf16 *__restrict__ lo, int n) {
    int i = blockIdx.x * blockDim.x + threadIdx.x;
    if (i < n) fsplit(in[i], hi[i], lo[i]);
}

__global__ void k_convW(const float *__restrict__ W, bf16 *__restrict__ whi,
                        bf16 *__restrict__ wlo, int K2, int M) {
    int i = blockIdx.x * blockDim.x + threadIdx.x;
    if (i < K2 * M) {
        int n = i / K2;
        int k = i - n * K2;
        fsplit(W[(size_t)k * M + n], whi[i], wlo[i]);
    }
}

// W3 [512][40] fp32 -> B3 [80][256] bf16 hi/lo, k-contiguous with stride CHID=256.
__global__ void k_convW3(const float *__restrict__ W3) {
    int i = blockIdx.x * blockDim.x + threadIdx.x;
    if (i < P3W * CHID) {
        int n = i / CHID;
        int k = i - n * CHID;
        float v = (n < COUT) ? W3[(size_t)k * COUT + n]
                             : W3[(size_t)(CHID + k) * COUT + (n - COUT)];
        fsplit(v, g_w3hi[i], g_w3lo[i]);
    }
}

// ---------------- aggregation (CSR, no atomics) ----------------
union U4 { uint2 u; bf16 b[4]; };
union U8 { uint4 u; bf16 b[8]; };

__global__ void k_agg128(const float *__restrict__ x) {
    int lane = threadIdx.x & 31, w = threadIdx.x >> 5;
    int node = blockIdx.x * 8 + w;
    if (node >= NN) return;
    int e0 = g_rowptr[node], e1 = g_rowptr[node + 1];
    float a0 = 0.f, a1 = 0.f, a2 = 0.f, a3 = 0.f;
    for (int e = e0; e < e1; e++) {
        int2  pk = g_cpack[e];
        float wt = __int_as_float(pk.y);
        float4 v = *(const float4 *)(x + (size_t)pk.x * CIN + lane * 4);
        a0 += wt * v.x; a1 += wt * v.y; a2 += wt * v.z; a3 += wt * v.w;
    }
    U4 oh, ol;
    fsplit(a0, oh.b[0], ol.b[0]);
    fsplit(a1, oh.b[1], ol.b[1]);
    fsplit(a2, oh.b[2], ol.b[2]);
    fsplit(a3, oh.b[3], ol.b[3]);
    size_t off = (size_t)node * CIN + lane * 4;
    *(uint2 *)(g_aghi + off) = oh.u;
    *(uint2 *)(g_aglo + off) = ol.u;
}

__global__ void k_agg256(const bf16 *__restrict__ hhi, const bf16 *__restrict__ hlo) {
    int lane = threadIdx.x & 31, w = threadIdx.x >> 5;
    int node = blockIdx.x * 8 + w;
    if (node >= NN) return;
    int e0 = g_rowptr[node], e1 = g_rowptr[node + 1];
    float acc[8];
#pragma unroll
    for (int j = 0; j < 8; j++) acc[j] = 0.f;
    for (int e = e0; e < e1; e++) {
        int2  pk = g_cpack[e];
        float wt = __int_as_float(pk.y);
        uint4 uh = *(const uint4 *)(hhi + (size_t)pk.x * CHID + lane * 8);
        uint4 ul = *(const uint4 *)(hlo + (size_t)pk.x * CHID + lane * 8);
        const bf162 *ph = (const bf162 *)&uh;
        const bf162 *pl = (const bf162 *)&ul;
#pragma unroll
        for (int j = 0; j < 4; j++) {
            float2 fh = __bfloat1622float2(ph[j]);
            float2 fl = __bfloat1622float2(pl[j]);
            acc[2 * j]     += wt * (fh.x + fl.x);
            acc[2 * j + 1] += wt * (fh.y + fl.y);
        }
    }
    U8 oh, ol;
#pragma unroll
    for (int j = 0; j < 8; j++) fsplit(acc[j], oh.b[j], ol.b[j]);
    size_t off = (size_t)node * CHID + lane * 8;
    *(uint4 *)(g_aghi + off) = oh.u;
    *(uint4 *)(g_aglo + off) = ol.u;
}

// ---------------- GEMM: 128 x (32*NT) block tile, 8 warps, 3-stage cp.async ----------------
// A0/A1: hi/lo bf16 [N, KPART] (two k-parts). B: hi/lo bf16 [NOUT][K2].
// Split product: C = Ahi*Bhi + Ahi*Blo + Alo*Bhi  (fp32 accum)
// Warp grid 2x4; warp tile 64 x (8*NT). A-frag registers are reused between the
// hi-products and the lo-product to fit 2 CTAs/SM.
#define STAGES 3

template <int K2, int KPART, int NOUT, int NT, bool SPLIT>
__global__ __launch_bounds__(256, 2) void k_gemm(
    const bf16 *__restrict__ Ah0, const bf16 *__restrict__ Al0,
    const bf16 *__restrict__ Ah1, const bf16 *__restrict__ Al1,
    const bf16 *__restrict__ Bh, const bf16 *__restrict__ Bl,
    const float *__restrict__ bias,
    bf16 *__restrict__ Chi, bf16 *__restrict__ Clo, float *__restrict__ Cf) {

    constexpr int BN = 32 * NT;
    // [stage][ Ah(128x16) | Al(128x16) | Bh(BNx16) | Bl(BNx16) ]
    __shared__ bf16 sm[STAGES][2 * (128 + BN) * 16];

    int tid = threadIdx.x, lane = tid & 31, warp = tid >> 5;
    int wm = warp >> 2, wn = warp & 3;            // 2 x 4 warp grid
    int rb = blockIdx.x, cb = blockIdx.y;

    const int KT = K2 / 16;

    float acc[4][NT][4];
#pragma unroll
    for (int a = 0; a < 4; a++)
#pragma unroll
        for (int b = 0; b < NT; b++)
#pragma unroll
            for (int c = 0; c < 4; c++) acc[a][b][c] = 0.f;

    // staging: thread t covers (row = t>>1, half = t&1)
    int sr = tid >> 1, sh = tid & 1;
    int a_gr = rb * 128 + sr;
    int b_gn = cb * BN + sr;
    bool a_ok = a_gr < NN;
    bool b_ok = (sr < BN) && (b_gn < NOUT);
    int a_grc = a_ok ? a_gr : 0;
    int b_gnc = b_ok ? b_gn : 0;

    auto issue = [&](int kt, int buf) {
        int part = (kt * 16 >= KPART) ? 1 : 0;
        int kcol = kt * 16 - part * KPART;
        const bf16 *Ah = part ? Ah1 : Ah0;
        const bf16 *Al = part ? Al1 : Al0;
        uint32_t base = (uint32_t)__cvta_generic_to_shared(&sm[buf][0]);
        uint32_t off  = (uint32_t)(sr * 16 + sh * 8) * 2;
        cp_async16(base + off,        Ah + (size_t)a_grc * KPART + kcol + sh * 8, a_ok);
        cp_async16(base + 4096 + off, Al + (size_t)a_grc * KPART + kcol + sh * 8, a_ok);
        if (sr < BN) {
            cp_async16(base + 8192 + off,
                       Bh + (size_t)b_gnc * K2 + kt * 16 + sh * 8, b_ok);
            cp_async16(base + 8192 + BN * 32 + off,
                       Bl + (size_t)b_gnc * K2 + kt * 16 + sh * 8, b_ok);
        }
    };

#pragma unroll
    for (int s = 0; s < STAGES - 1; s++) {
        issue(s, s);
        cp_commit();
    }

    for (int kt = 0; kt < KT; kt++) {
        cp_wait<STAGES - 2>();
        __syncthreads();
        int nk = kt + STAGES - 1;
        if (nk < KT) issue(nk, nk % STAGES);
        cp_commit();

        int buf = kt % STAGES;
        const uint32_t *A32h = (const uint32_t *)(sm[buf]);
        const uint32_t *A32l = (const uint32_t *)(sm[buf] + 128 * 16);
        const uint32_t *B32h = (const uint32_t *)(sm[buf] + 2 * 128 * 16);
        const uint32_t *B32l = (const uint32_t *)(sm[buf] + 2 * 128 * 16 + BN * 16);

        int rbase = wm * 64 + (lane >> 2);
        int kq    = lane & 3;
        int nb0   = wn * (8 * NT) + (lane >> 2);

        uint32_t bh[NT][2], bl[NT][2];
#pragma unroll
        for (int nt = 0; nt < NT; nt++) {
            int nnr = nb0 + nt * 8;
            bh[nt][0] = B32h[nnr * 8 + kq];
            bh[nt][1] = B32h[nnr * 8 + kq + 4];
            bl[nt][0] = B32l[nnr * 8 + kq];
            bl[nt][1] = B32l[nnr * 8 + kq + 4];
        }

        uint32_t af[4][4];
        // A-hi products
#pragma unroll
        for (int mt = 0; mt < 4; mt++) {
            int rr = rbase + mt * 16;
            af[mt][0] = A32h[rr * 8 + kq];
            af[mt][1] = A32h[(rr + 8) * 8 + kq];
            af[mt][2] = A32h[rr * 8 + kq + 4];
            af[mt][3] = A32h[(rr + 8) * 8 + kq + 4];
        }
#pragma unroll
        for (int mt = 0; mt < 4; mt++)
#pragma unroll
            for (int nt = 0; nt < NT; nt++) {
                mma16816(acc[mt][nt], af[mt], bh[nt]);
                mma16816(acc[mt][nt], af[mt], bl[nt]);
            }
        // A-lo product (reuse af registers)
#pragma unroll
        for (int mt = 0; mt < 4; mt++) {
            int rr = rbase + mt * 16;
            af[mt][0] = A32l[rr * 8 + kq];
            af[mt][1] = A32l[(rr + 8) * 8 + kq];
            af[mt][2] = A32l[rr * 8 + kq + 4];
            af[mt][3] = A32l[(rr + 8) * 8 + kq + 4];
        }
#pragma unroll
        for (int mt = 0; mt < 4; mt++)
#pragma unroll
            for (int nt = 0; nt < NT; nt++)
                mma16816(acc[mt][nt], af[mt], bh[nt]);
        // NOTE: no trailing __syncthreads — the barrier at the top of the next
        // iteration (after cp_wait) already orders all warps' reads of this
        // buffer before any warp's cp.async re-fills it (3-stage rotation).
    }

    // epilogue
#pragma unroll
    for (int mt = 0; mt < 4; mt++)
#pragma unroll
        for (int nt = 0; nt < NT; nt++) {
            int r0 = rb * 128 + wm * 64 + mt * 16 + (lane >> 2);
            int c0 = cb * BN + wn * (8 * NT) + nt * 8 + (lane & 3) * 2;
            float *cc = acc[mt][nt];
            if (SPLIT) {
                float b0 = bias[c0], b1 = bias[c0 + 1];
                if (r0 < NN) {
                    float v0 = fmaxf(cc[0] + b0, 0.f), v1 = fmaxf(cc[1] + b1, 0.f);
                    bf16 h0, l0, h1, l1;
                    fsplit(v0, h0, l0); fsplit(v1, h1, l1);
                    *(bf162 *)(Chi + (size_t)r0 * CHID + c0) = __halves2bfloat162(h0, h1);
                    *(bf162 *)(Clo + (size_t)r0 * CHID + c0) = __halves2bfloat162(l0, l1);
                }
                if (r0 + 8 < NN) {
                    float v0 = fmaxf(cc[2] + b0, 0.f), v1 = fmaxf(cc[3] + b1, 0.f);
                    bf16 h0, l0, h1, l1;
                    fsplit(v0, h0, l0); fsplit(v1, h1, l1);
                    *(bf162 *)(Chi + (size_t)(r0 + 8) * CHID + c0) = __halves2bfloat162(h0, h1);
                    *(bf162 *)(Clo + (size_t)(r0 + 8) * CHID + c0) = __halves2bfloat162(l0, l1);
                }
            } else {
                if (r0 < NN) {
                    if (c0 < NOUT)     Cf[(size_t)r0 * NOUT + c0]     = cc[0];
                    if (c0 + 1 < NOUT) Cf[(size_t)r0 * NOUT + c0 + 1] = cc[1];
                }
                if (r0 + 8 < NN) {
                    if (c0 < NOUT)     Cf[(size_t)(r0 + 8) * NOUT + c0]     = cc[2];
                    if (c0 + 1 < NOUT) Cf[(size_t)(r0 + 8) * NOUT + c0 + 1] = cc[3];
                }
            }
        }
}

// ---------------- fused layer-3 tail: agg(d=40) + self + bias + log_softmax ----------------
__global__ void k_final(const float *__restrict__ b3, float *__restrict__ out) {
    int w = threadIdx.x >> 5, lane = threadIdx.x & 31;
    int node = blockIdx.x * 8 + w;
    if (node >= NN) return;
    int e0 = g_rowptr[node], e1 = g_rowptr[node + 1];
    float a0 = 0.f, a1 = 0.f;
    for (int e = e0; e < e1; e++) {
        int2  pk = g_cpack[e];
        float wt = __int_as_float(pk.y);
        const float *pb = g_p3 + (size_t)pk.x * P3W + COUT;
        a0 += wt * pb[lane];
        if (lane < 8) a1 += wt * pb[32 + lane];
    }
    const float *ps = g_p3 + (size_t)node * P3W;
    float v1 = ps[lane] + a0 + b3[lane];
    float v2 = (lane < 8) ? ps[32 + lane] + a1 + b3[32 + lane] : -INFINITY;
    float m = fmaxf(v1, v2);
#pragma unroll
    for (int o = 16; o; o >>= 1) m = fmaxf(m, __shfl_xor_sync(0xffffffffu, m, o));
    float s = expf(v1 - m) + ((lane < 8) ? expf(v2 - m) : 0.f);
#pragma unroll
    for (int o = 16; o; o >>= 1) s += __shfl_xor_sync(0xffffffffu, s, o);
    float lse = m + logf(s);
    out[(size_t)node * COUT + lane] = v1 - lse;
    if (lane < 8) out[(size_t)node * COUT + 32 + lane] = v2 - lse;
}

// ---------------- launch ----------------
#define SYM(p, s) cudaGetSymbolAddress((void **)&(p), s)

extern "C" void kernel_launch(void *const *d_in, const int *in_sizes, int n_in,
                              void *d_out, int out_size) {
    const float *x  = (const float *)d_in[0];
    const int   *ei = (const int *)d_in[1];
    const float *ew = (const float *)d_in[2];
    const float *W1 = (const float *)d_in[3];
    const float *b1 = (const float *)d_in[4];
    const float *W2 = (const float *)d_in[5];
    const float *b2 = (const float *)d_in[6];
    const float *W3 = (const float *)d_in[7];
    const float *b3 = (const float *)d_in[8];
    float *out = (float *)d_out;
    const int *src = ei;
    const int *dst = ei + NE;

    bf16 *xhi, *xlo, *h1hi, *h1lo, *h2hi, *h2lo, *aghi, *aglo;
    bf16 *w1hi, *w1lo, *w2hi, *w2lo, *w3hi, *w3lo;
    float *p3;
    SYM(xhi, g_xhi);   SYM(xlo, g_xlo);
    SYM(h1hi, g_h1hi); SYM(h1lo, g_h1lo);
    SYM(h2hi, g_h2hi); SYM(h2lo, g_h2lo);
    SYM(aghi, g_aghi); SYM(aglo, g_aglo);
    SYM(w1hi, g_w1hi); SYM(w1lo, g_w1lo);
    SYM(w2hi, g_w2hi); SYM(w2lo, g_w2lo);
    SYM(w3hi, g_w3hi); SYM(w3lo, g_w3lo);
    SYM(p3, g_p3);

    // CSR build
    k_zero_deg<<<(NN + 255) / 256, 256>>>();
    k_hist<<<(NE + 255) / 256, 256>>>(dst);
    k_scan1<<<SCAN_NB, SCAN_T>>>();
    k_scan2<<<1, 128>>>();
    k_scan3<<<SCAN_NB, SCAN_T>>>();
    k_fill<<<(NE + 255) / 256, 256>>>(src, dst, ew);

    // conversions
    k_split<<<(NN * CIN + 255) / 256, 256>>>(x, xhi, xlo, NN * CIN);
    k_convW<<<(CHID * 2 * CIN + 255) / 256, 256>>>(W1, w1hi, w1lo, 2 * CIN, CHID);
    k_convW<<<(CHID * 2 * CHID + 255) / 256, 256>>>(W2, w2hi, w2lo, 2 * CHID, CHID);
    k_convW3<<<(P3W * CHID + 255) / 256, 256>>>(W3);

    dim3 gHID((NN + 127) / 128, 2);
    dim3 gP3((NN + 127) / 128, 1);

    // layer 1
    k_agg128<<<(NN + 7) / 8, 256>>>(x);
    k_gemm<256, CIN, CHID, 4, true><<<gHID, 256>>>(xhi, xlo, aghi, aglo, w1hi, w1lo, b1,
                                                   h1hi, h1lo, nullptr);
    // layer 2
    k_agg256<<<(NN + 7) / 8, 256>>>(h1hi, h1lo);
    k_gemm<512, CHID, CHID, 4, true><<<gHID, 256>>>(h1hi, h1lo, aghi, aglo, w2hi, w2lo, b2,
                                                    h2hi, h2lo, nullptr);
    // layer 3: GEMM first (h2 @ [W3_top|W3_bot] -> P[100k][80]), then fused agg tail
    k_gemm<256, 256, P3W, 3, false><<<gP3, 256>>>(h2hi, h2lo, h2hi, h2lo, w3hi, w3lo, nullptr,
                                                  nullptr, nullptr, p3);
    k_final<<<(NN + 7) / 8, 256>>>(b3, out);
}

// round 8
// speedup vs baseline: 1.6814x; 1.1123x over previous
#include <cuda_runtime.h>
#include <cuda_bf16.h>
#include <stdint.h>
#include <math.h>

#define NN   100000
#define NE   1600000
#define CIN  128
#define CHID 256
#define COUT 40
#define P3W  80          // layer-3 pre-agg width (40 self + 40 agg-input)

typedef __nv_bfloat16  bf16;
typedef __nv_bfloat162 bf162;

#define SCAN_T  1024
#define SCAN_NB ((NN + SCAN_T - 1) / SCAN_T)   // 98

// ---------------- device scratch ----------------
__device__ int   g_deg[NN];
__device__ int   g_rowptr[NN + 1];
__device__ int   g_cursor[NN];
__device__ int   g_bsums[SCAN_NB];
__device__ int2  g_cpack[NE];          // (src, weight bits)

__device__ bf16  g_xhi[(size_t)NN * CIN];
__device__ bf16  g_xlo[(size_t)NN * CIN];
__device__ bf16  g_h1hi[(size_t)NN * CHID];
__device__ bf16  g_h1lo[(size_t)NN * CHID];
__device__ bf16  g_h2hi[(size_t)NN * CHID];
__device__ bf16  g_h2lo[(size_t)NN * CHID];
__device__ bf16  g_aghi[(size_t)NN * CHID];
__device__ bf16  g_aglo[(size_t)NN * CHID];

__device__ bf16  g_w1hi[CHID * 2 * CIN];
__device__ bf16  g_w1lo[CHID * 2 * CIN];
__device__ bf16  g_w2hi[CHID * 2 * CHID];
__device__ bf16  g_w2lo[CHID * 2 * CHID];
__device__ bf16  g_w3hi[P3W * CHID];          // [80][256], k-contiguous (K2=256)
__device__ bf16  g_w3lo[P3W * CHID];

__device__ float g_p3[(size_t)NN * P3W];

// ---------------- helpers ----------------
__device__ __forceinline__ void fsplit(float v, bf16 &hi, bf16 &lo) {
    hi = __float2bfloat16(v);
    lo = __float2bfloat16(v - __bfloat162float(hi));
}

__device__ __forceinline__ void mma16816(float *c, const uint32_t *a, const uint32_t *b) {
    asm volatile(
        "mma.sync.aligned.m16n8k16.row.col.f32.bf16.bf16.f32 "
        "{%0,%1,%2,%3}, {%4,%5,%6,%7}, {%8,%9}, {%0,%1,%2,%3};\n"
        : "+f"(c[0]), "+f"(c[1]), "+f"(c[2]), "+f"(c[3])
        : "r"(a[0]), "r"(a[1]), "r"(a[2]), "r"(a[3]), "r"(b[0]), "r"(b[1]));
}

__device__ __forceinline__ void ldsm_x4(uint32_t *r, uint32_t a) {
    asm volatile("ldmatrix.sync.aligned.m8n8.x4.shared.b16 {%0,%1,%2,%3}, [%4];"
                 : "=r"(r[0]), "=r"(r[1]), "=r"(r[2]), "=r"(r[3]) : "r"(a));
}
__device__ __forceinline__ void ldsm_x2(uint32_t *r, uint32_t a) {
    asm volatile("ldmatrix.sync.aligned.m8n8.x2.shared.b16 {%0,%1}, [%2];"
                 : "=r"(r[0]), "=r"(r[1]) : "r"(a));
}

__device__ __forceinline__ void cp_async16(uint32_t d, const void *s, bool p) {
    asm volatile("cp.async.cg.shared.global [%0], [%1], 16, %2;\n"
                 :: "r"(d), "l"(s), "r"(p ? 16 : 0));
}
__device__ __forceinline__ void cp_commit() { asm volatile("cp.async.commit_group;\n"); }
template <int N> __device__ __forceinline__ void cp_wait() {
    asm volatile("cp.async.wait_group %0;\n" :: "n"(N));
}

// 16B-granular XOR swizzle on 32B rows: conflict-free for both cp.async stores
// and ldmatrix phases.  sw(row, half) = row*32 + ((half ^ ((row>>2)&1)) << 4)
__device__ __forceinline__ uint32_t sw_off(int row, int half) {
    return (uint32_t)(row * 32 + ((half ^ ((row >> 2) & 1)) << 4));
}

// ---------------- CSR build ----------------
__global__ void k_zero_deg() {
    int i = blockIdx.x * blockDim.x + threadIdx.x;
    if (i < NN) g_deg[i] = 0;
}

__global__ void k_hist(const int *__restrict__ dst) {
    int e = blockIdx.x * blockDim.x + threadIdx.x;
    if (e < NE) atomicAdd(&g_deg[dst[e]], 1);
}

__global__ void k_scan1() {
    __shared__ int s[SCAN_T];
    int t = threadIdx.x;
    int g = blockIdx.x * SCAN_T + t;
    int v = (g < NN) ? g_deg[g] : 0;
    s[t] = v;
    __syncthreads();
    for (int o = 1; o < SCAN_T; o <<= 1) {
        int x = (t >= o) ? s[t - o] : 0;
        __syncthreads();
        s[t] += x;
        __syncthreads();
    }
    if (g < NN) g_rowptr[g + 1] = s[t];
    if (t == SCAN_T - 1) g_bsums[blockIdx.x] = s[t];
}

__global__ void k_scan2() {
    __shared__ int s[128];
    int t = threadIdx.x;
    int v = (t < SCAN_NB) ? g_bsums[t] : 0;
    s[t] = v;
    __syncthreads();
    for (int o = 1; o < 128; o <<= 1) {
        int x = (t >= o) ? s[t - o] : 0;
        __syncthreads();
        s[t] += x;
        __syncthreads();
    }
    if (t < SCAN_NB) g_bsums[t] = s[t] - v;
}

__global__ void k_scan3() {
    int g = blockIdx.x * SCAN_T + threadIdx.x;
    if (g < NN) {
        int v = g_rowptr[g + 1] + g_bsums[blockIdx.x];
        g_rowptr[g + 1] = v;
        g_cursor[g] = v - g_deg[g];
    }
    if (g == 0) g_rowptr[0] = 0;
}

__global__ void k_fill(const int *__restrict__ src, const int *__restrict__ dst,
                       const float *__restrict__ ew) {
    int e = blockIdx.x * blockDim.x + threadIdx.x;
    if (e < NE) {
        int d = dst[e];
        int p = atomicAdd(&g_cursor[d], 1);
        g_cpack[p] = make_int2(src[e], __float_as_int(ew[e]));
    }
}

// ---------------- conversions ----------------
__global__ void k_split(const float *__restrict__ in, bf16 *__restrict__ hi,
                        bf16 *__restrict__ lo, int n) {
    int i = blockIdx.x * blockDim.x + threadIdx.x;
    if (i < n) fsplit(in[i], hi[i], lo[i]);
}

__global__ void k_convW(const float *__restrict__ W, bf16 *__restrict__ whi,
                        bf16 *__restrict__ wlo, int K2, int M) {
    int i = blockIdx.x * blockDim.x + threadIdx.x;
    if (i < K2 * M) {
        int n = i / K2;
        int k = i - n * K2;
        fsplit(W[(size_t)k * M + n], whi[i], wlo[i]);
    }
}

// W3 [512][40] fp32 -> B3 [80][256] bf16 hi/lo, k-contiguous with stride CHID=256.
__global__ void k_convW3(const float *__restrict__ W3) {
    int i = blockIdx.x * blockDim.x + threadIdx.x;
    if (i < P3W * CHID) {
        int n = i / CHID;
        int k = i - n * CHID;
        float v = (n < COUT) ? W3[(size_t)k * COUT + n]
                             : W3[(size_t)(CHID + k) * COUT + (n - COUT)];
        fsplit(v, g_w3hi[i], g_w3lo[i]);
    }
}

// ---------------- aggregation (CSR, no atomics) ----------------
union U4 { uint2 u; bf16 b[4]; };
union U8 { uint4 u; bf16 b[8]; };

__global__ void k_agg128(const float *__restrict__ x) {
    int lane = threadIdx.x & 31, w = threadIdx.x >> 5;
    int node = blockIdx.x * 8 + w;
    if (node >= NN) return;
    int e0 = g_rowptr[node], e1 = g_rowptr[node + 1];
    float a0 = 0.f, a1 = 0.f, a2 = 0.f, a3 = 0.f;
    for (int e = e0; e < e1; e++) {
        int2  pk = g_cpack[e];
        float wt = __int_as_float(pk.y);
        float4 v = *(const float4 *)(x + (size_t)pk.x * CIN + lane * 4);
        a0 += wt * v.x; a1 += wt * v.y; a2 += wt * v.z; a3 += wt * v.w;
    }
    U4 oh, ol;
    fsplit(a0, oh.b[0], ol.b[0]);
    fsplit(a1, oh.b[1], ol.b[1]);
    fsplit(a2, oh.b[2], ol.b[2]);
    fsplit(a3, oh.b[3], ol.b[3]);
    size_t off = (size_t)node * CIN + lane * 4;
    *(uint2 *)(g_aghi + off) = oh.u;
    *(uint2 *)(g_aglo + off) = ol.u;
}

__global__ void k_agg256(const bf16 *__restrict__ hhi, const bf16 *__restrict__ hlo) {
    int lane = threadIdx.x & 31, w = threadIdx.x >> 5;
    int node = blockIdx.x * 8 + w;
    if (node >= NN) return;
    int e0 = g_rowptr[node], e1 = g_rowptr[node + 1];
    float acc[8];
#pragma unroll
    for (int j = 0; j < 8; j++) acc[j] = 0.f;
    for (int e = e0; e < e1; e++) {
        int2  pk = g_cpack[e];
        float wt = __int_as_float(pk.y);
        uint4 uh = *(const uint4 *)(hhi + (size_t)pk.x * CHID + lane * 8);
        uint4 ul = *(const uint4 *)(hlo + (size_t)pk.x * CHID + lane * 8);
        const bf162 *ph = (const bf162 *)&uh;
        const bf162 *pl = (const bf162 *)&ul;
#pragma unroll
        for (int j = 0; j < 4; j++) {
            float2 fh = __bfloat1622float2(ph[j]);
            float2 fl = __bfloat1622float2(pl[j]);
            acc[2 * j]     += wt * (fh.x + fl.x);
            acc[2 * j + 1] += wt * (fh.y + fl.y);
        }
    }
    U8 oh, ol;
#pragma unroll
    for (int j = 0; j < 8; j++) fsplit(acc[j], oh.b[j], ol.b[j]);
    size_t off = (size_t)node * CHID + lane * 8;
    *(uint4 *)(g_aghi + off) = oh.u;
    *(uint4 *)(g_aglo + off) = ol.u;
}

// ---------------- GEMM: 128 x (32*NT) block tile, 8 warps, 3-stage cp.async ----------------
// A0/A1: hi/lo bf16 [N, KPART] (two k-parts). B: hi/lo bf16 [NOUT][K2].
// Split product: C = Ahi*Bhi + Ahi*Blo + Alo*Bhi  (fp32 accum)
// Fragments loaded via ldmatrix (swizzled smem); warp grid 2x4, warp tile 64x(8*NT).
#define STAGES 3

template <int K2, int KPART, int NOUT, int NT, bool SPLIT>
__global__ __launch_bounds__(256, 2) void k_gemm(
    const bf16 *__restrict__ Ah0, const bf16 *__restrict__ Al0,
    const bf16 *__restrict__ Ah1, const bf16 *__restrict__ Al1,
    const bf16 *__restrict__ Bh, const bf16 *__restrict__ Bl,
    const float *__restrict__ bias,
    bf16 *__restrict__ Chi, bf16 *__restrict__ Clo, float *__restrict__ Cf) {

    constexpr int BN = 32 * NT;
    // [stage][ Ah(128x16) | Al(128x16) | Bh(BNx16) | Bl(BNx16) ] rows of 32B, swizzled
    __shared__ bf16 sm[STAGES][2 * (128 + BN) * 16];

    int tid = threadIdx.x, lane = tid & 31, warp = tid >> 5;
    int wm = warp >> 2, wn = warp & 3;            // 2 x 4 warp grid
    int rb = blockIdx.x, cb = blockIdx.y;

    const int KT = K2 / 16;

    float acc[4][NT][4];
#pragma unroll
    for (int a = 0; a < 4; a++)
#pragma unroll
        for (int b = 0; b < NT; b++)
#pragma unroll
            for (int c = 0; c < 4; c++) acc[a][b][c] = 0.f;

    // staging: thread t covers (row = t>>1, half = t&1)
    int sr = tid >> 1, sh = tid & 1;
    int a_gr = rb * 128 + sr;
    int b_gn = cb * BN + sr;
    bool a_ok = a_gr < NN;
    bool b_ok = (sr < BN) && (b_gn < NOUT);
    int a_grc = a_ok ? a_gr : 0;
    int b_gnc = b_ok ? b_gn : 0;
    uint32_t st_off = sw_off(sr, sh);             // swizzled 16B-chunk offset

    auto issue = [&](int kt, int buf) {
        int part = (kt * 16 >= KPART) ? 1 : 0;
        int kcol = kt * 16 - part * KPART;
        const bf16 *Ah = part ? Ah1 : Ah0;
        const bf16 *Al = part ? Al1 : Al0;
        uint32_t base = (uint32_t)__cvta_generic_to_shared(&sm[buf][0]);
        cp_async16(base + st_off,        Ah + (size_t)a_grc * KPART + kcol + sh * 8, a_ok);
        cp_async16(base + 4096 + st_off, Al + (size_t)a_grc * KPART + kcol + sh * 8, a_ok);
        if (sr < BN) {
            cp_async16(base + 8192 + st_off,
                       Bh + (size_t)b_gnc * K2 + kt * 16 + sh * 8, b_ok);
            cp_async16(base + 8192 + BN * 32 + st_off,
                       Bl + (size_t)b_gnc * K2 + kt * 16 + sh * 8, b_ok);
        }
    };

#pragma unroll
    for (int s = 0; s < STAGES - 1; s++) {
        issue(s, s);
        cp_commit();
    }

    // per-lane ldmatrix address offsets (swizzle bit is lane-constant because all
    // tile-base rows are multiples of 8 with even row>>2)
    int liA = lane & 15, hbA = lane >> 4;
    uint32_t loffA = (uint32_t)(liA * 32 + ((hbA ^ ((liA >> 2) & 1)) << 4));
    int liB = (lane & 7) + ((lane >> 4) << 3);
    int hbB = (lane >> 3) & 1;
    uint32_t loffB = (uint32_t)(liB * 32 + ((hbB ^ ((liB >> 2) & 1)) << 4));

    for (int kt = 0; kt < KT; kt++) {
        cp_wait<STAGES - 2>();
        __syncthreads();
        int nk = kt + STAGES - 1;
        if (nk < KT) issue(nk, nk % STAGES);
        cp_commit();

        int buf = kt % STAGES;
        uint32_t smb = (uint32_t)__cvta_generic_to_shared(&sm[buf][0]);
        uint32_t Ahb = smb,            Alb = smb + 4096;
        uint32_t Bhb = smb + 8192,     Blb = smb + 8192 + BN * 32;

        uint32_t bh[NT][2], bl[NT][2];
#pragma unroll
        for (int p = 0; p < NT / 2; p++) {
            uint32_t ro = (uint32_t)(wn * (8 * NT) + p * 16) * 32;
            ldsm_x4(&bh[2 * p][0], Bhb + ro + loffB);
            ldsm_x4(&bl[2 * p][0], Blb + ro + loffB);
        }
        if (NT & 1) {
            uint32_t ro = (uint32_t)(wn * (8 * NT) + (NT - 1) * 8) * 32;
            ldsm_x2(&bh[NT - 1][0], Bhb + ro + loffB);
            ldsm_x2(&bl[NT - 1][0], Blb + ro + loffB);
        }

        uint32_t af[4][4];
        // A-hi products
#pragma unroll
        for (int mt = 0; mt < 4; mt++)
            ldsm_x4(af[mt], Ahb + (uint32_t)(wm * 64 + mt * 16) * 32 + loffA);
#pragma unroll
        for (int mt = 0; mt < 4; mt++)
#pragma unroll
            for (int nt = 0; nt < NT; nt++) {
                mma16816(acc[mt][nt], af[mt], bh[nt]);
                mma16816(acc[mt][nt], af[mt], bl[nt]);
            }
        // A-lo product (reuse af registers)
#pragma unroll
        for (int mt = 0; mt < 4; mt++)
            ldsm_x4(af[mt], Alb + (uint32_t)(wm * 64 + mt * 16) * 32 + loffA);
#pragma unroll
        for (int mt = 0; mt < 4; mt++)
#pragma unroll
            for (int nt = 0; nt < NT; nt++)
                mma16816(acc[mt][nt], af[mt], bh[nt]);
        // no trailing __syncthreads: top-of-iteration barrier orders buffer reuse
        // (3-stage rotation; validated in round 7)
    }

    // epilogue
#pragma unroll
    for (int mt = 0; mt < 4; mt++)
#pragma unroll
        for (int nt = 0; nt < NT; nt++) {
            int r0 = rb * 128 + wm * 64 + mt * 16 + (lane >> 2);
            int c0 = cb * BN + wn * (8 * NT) + nt * 8 + (lane & 3) * 2;
            float *cc = acc[mt][nt];
            if (SPLIT) {
                float b0 = bias[c0], b1 = bias[c0 + 1];
                if (r0 < NN) {
                    float v0 = fmaxf(cc[0] + b0, 0.f), v1 = fmaxf(cc[1] + b1, 0.f);
                    bf16 h0, l0, h1, l1;
                    fsplit(v0, h0, l0); fsplit(v1, h1, l1);
                    *(bf162 *)(Chi + (size_t)r0 * CHID + c0) = __halves2bfloat162(h0, h1);
                    *(bf162 *)(Clo + (size_t)r0 * CHID + c0) = __halves2bfloat162(l0, l1);
                }
                if (r0 + 8 < NN) {
                    float v0 = fmaxf(cc[2] + b0, 0.f), v1 = fmaxf(cc[3] + b1, 0.f);
                    bf16 h0, l0, h1, l1;
                    fsplit(v0, h0, l0); fsplit(v1, h1, l1);
                    *(bf162 *)(Chi + (size_t)(r0 + 8) * CHID + c0) = __halves2bfloat162(h0, h1);
                    *(bf162 *)(Clo + (size_t)(r0 + 8) * CHID + c0) = __halves2bfloat162(l0, l1);
                }
            } else {
                if (r0 < NN) {
                    if (c0 < NOUT)     Cf[(size_t)r0 * NOUT + c0]     = cc[0];
                    if (c0 + 1 < NOUT) Cf[(size_t)r0 * NOUT + c0 + 1] = cc[1];
                }
                if (r0 + 8 < NN) {
                    if (c0 < NOUT)     Cf[(size_t)(r0 + 8) * NOUT + c0]     = cc[2];
                    if (c0 + 1 < NOUT) Cf[(size_t)(r0 + 8) * NOUT + c0 + 1] = cc[3];
                }
            }
        }
}

// ---------------- fused layer-3 tail: agg(d=40) + self + bias + log_softmax ----------------
__global__ void k_final(const float *__restrict__ b3, float *__restrict__ out) {
    int w = threadIdx.x >> 5, lane = threadIdx.x & 31;
    int node = blockIdx.x * 8 + w;
    if (node >= NN) return;
    int e0 = g_rowptr[node], e1 = g_rowptr[node + 1];
    float a0 = 0.f, a1 = 0.f;
    for (int e = e0; e < e1; e++) {
        int2  pk = g_cpack[e];
        float wt = __int_as_float(pk.y);
        const float *pb = g_p3 + (size_t)pk.x * P3W + COUT;
        a0 += wt * pb[lane];
        if (lane < 8) a1 += wt * pb[32 + lane];
    }
    const float *ps = g_p3 + (size_t)node * P3W;
    float v1 = ps[lane] + a0 + b3[lane];
    float v2 = (lane < 8) ? ps[32 + lane] + a1 + b3[32 + lane] : -INFINITY;
    float m = fmaxf(v1, v2);
#pragma unroll
    for (int o = 16; o; o >>= 1) m = fmaxf(m, __shfl_xor_sync(0xffffffffu, m, o));
    float s = expf(v1 - m) + ((lane < 8) ? expf(v2 - m) : 0.f);
#pragma unroll
    for (int o = 16; o; o >>= 1) s += __shfl_xor_sync(0xffffffffu, s, o);
    float lse = m + logf(s);
    out[(size_t)node * COUT + lane] = v1 - lse;
    if (lane < 8) out[(size_t)node * COUT + 32 + lane] = v2 - lse;
}

// ---------------- launch ----------------
#define SYM(p, s) cudaGetSymbolAddress((void **)&(p), s)

extern "C" void kernel_launch(void *const *d_in, const int *in_sizes, int n_in,
                              void *d_out, int out_size) {
    const float *x  = (const float *)d_in[0];
    const int   *ei = (const int *)d_in[1];
    const float *ew = (const float *)d_in[2];
    const float *W1 = (const float *)d_in[3];
    const float *b1 = (const float *)d_in[4];
    const float *W2 = (const float *)d_in[5];
    const float *b2 = (const float *)d_in[6];
    const float *W3 = (const float *)d_in[7];
    const float *b3 = (const float *)d_in[8];
    float *out = (float *)d_out;
    const int *src = ei;
    const int *dst = ei + NE;

    bf16 *xhi, *xlo, *h1hi, *h1lo, *h2hi, *h2lo, *aghi, *aglo;
    bf16 *w1hi, *w1lo, *w2hi, *w2lo, *w3hi, *w3lo;
    float *p3;
    SYM(xhi, g_xhi);   SYM(xlo, g_xlo);
    SYM(h1hi, g_h1hi); SYM(h1lo, g_h1lo);
    SYM(h2hi, g_h2hi); SYM(h2lo, g_h2lo);
    SYM(aghi, g_aghi); SYM(aglo, g_aglo);
    SYM(w1hi, g_w1hi); SYM(w1lo, g_w1lo);
    SYM(w2hi, g_w2hi); SYM(w2lo, g_w2lo);
    SYM(w3hi, g_w3hi); SYM(w3lo, g_w3lo);
    SYM(p3, g_p3);

    // CSR build
    k_zero_deg<<<(NN + 255) / 256, 256>>>();
    k_hist<<<(NE + 255) / 256, 256>>>(dst);
    k_scan1<<<SCAN_NB, SCAN_T>>>();
    k_scan2<<<1, 128>>>();
    k_scan3<<<SCAN_NB, SCAN_T>>>();
    k_fill<<<(NE + 255) / 256, 256>>>(src, dst, ew);

    // conversions
    k_split<<<(NN * CIN + 255) / 256, 256>>>(x, xhi, xlo, NN * CIN);
    k_convW<<<(CHID * 2 * CIN + 255) / 256, 256>>>(W1, w1hi, w1lo, 2 * CIN, CHID);
    k_convW<<<(CHID * 2 * CHID + 255) / 256, 256>>>(W2, w2hi, w2lo, 2 * CHID, CHID);
    k_convW3<<<(P3W * CHID + 255) / 256, 256>>>(W3);

    dim3 gHID((NN + 127) / 128, 2);
    dim3 gP3((NN + 127) / 128, 1);

    // layer 1
    k_agg128<<<(NN + 7) / 8, 256>>>(x);
    k_gemm<256, CIN, CHID, 4, true><<<gHID, 256>>>(xhi, xlo, aghi, aglo, w1hi, w1lo, b1,
                                                   h1hi, h1lo, nullptr);
    // layer 2
    k_agg256<<<(NN + 7) / 8, 256>>>(h1hi, h1lo);
    k_gemm<512, CHID, CHID, 4, true><<<gHID, 256>>>(h1hi, h1lo, aghi, aglo, w2hi, w2lo, b2,
                                                    h2hi, h2lo, nullptr);
    // layer 3: GEMM first (h2 @ [W3_top|W3_bot] -> P[100k][80]), then fused agg tail
    k_gemm<256, 256, P3W, 3, false><<<gP3, 256>>>(h2hi, h2lo, h2hi, h2lo, w3hi, w3lo, nullptr,
                                                  nullptr, nullptr, p3);
    k_final<<<(NN + 7) / 8, 256>>>(b3, out);
}